// round 3
// baseline (speedup 1.0000x reference)
#include <cuda_runtime.h>

#define NN 50000
#define NE 800000
#define IN_CH 512
#define HID 256
#define OUTC 128

// ---- scratch (static device globals; no allocations allowed) ----
__device__ float g_deg[NN];                       // deg -> dinv in place
__device__ float g_h1[(size_t)NN * HID];         // x @ W1
__device__ float g_agg1[(size_t)NN * HID];       // aggregated + relu
__device__ float g_h2[(size_t)NN * OUTC];        // agg1 @ W2
__device__ int   g_is64;                          // edge_index dtype flag

// ---------------------------------------------------------------------------
// dtype detection: int64 node ids (< 2^31) have all-zero odd 32-bit words;
// random int32 ids in [0, 50000) cannot. Deterministic pure function of input.
// ---------------------------------------------------------------------------
__global__ void k_flag_init() { g_is64 = 1; }

__global__ void k_detect(const unsigned int* __restrict__ w) {
    unsigned acc = 0;
    for (int i = threadIdx.x; i < 2048; i += blockDim.x) acc |= w[2 * i + 1];
    if (acc) g_is64 = 0;                      // any nonzero odd word -> int32
}

__device__ __forceinline__ int edge_idx(const void* ei, size_t pos, int is64) {
    long long v = is64 ? ((const long long*)ei)[pos]
                       : (long long)((const int*)ei)[pos];
    int i = (int)v;
    i = i < 0 ? 0 : (i >= NN ? NN - 1 : i);   // clamp: trap insurance
    return i;
}

// ---------------------------------------------------------------------------
// degree / normalization
// ---------------------------------------------------------------------------
__global__ void k_deg_init(float* deg) {
    int i = blockIdx.x * blockDim.x + threadIdx.x;
    if (i < NN) deg[i] = 1.0f;   // self-loop contributes 1
}

__global__ void k_deg_accum(const void* __restrict__ ei, float* deg) {
    int e = blockIdx.x * blockDim.x + threadIdx.x;
    if (e >= NE) return;
    int is64 = g_is64;
    atomicAdd(&deg[edge_idx(ei, (size_t)NE + e, is64)], 1.0f);   // dst row
}

__global__ void k_dinv(float* deg) {
    int i = blockIdx.x * blockDim.x + threadIdx.x;
    if (i < NN) deg[i] = rsqrtf(deg[i]);   // deg >= 1 always (self-loops)
}

// ---------------------------------------------------------------------------
// SGEMM: C[M,N] = A[M,K] @ B[K,N], fp32, 128x128x16 tile, 8x8 per thread
// ---------------------------------------------------------------------------
__global__ __launch_bounds__(256, 2)
void sgemm_128x128(const float* __restrict__ A, const float* __restrict__ B,
                   float* __restrict__ C, int M, int N, int K) {
    __shared__ float As[16][129];                 // transposed, padded
    __shared__ __align__(16) float Bs[16][128];

    const int tid  = threadIdx.x;
    const int brow = blockIdx.x * 128;
    const int bcol = blockIdx.y * 128;
    const int trow = (tid >> 4) * 8;
    const int tcol = (tid & 15) * 8;

    float acc[8][8];
#pragma unroll
    for (int i = 0; i < 8; i++)
#pragma unroll
        for (int j = 0; j < 8; j++) acc[i][j] = 0.0f;

    for (int k0 = 0; k0 < K; k0 += 16) {
#pragma unroll
        for (int i = 0; i < 2; i++) {
            int idx = i * 256 + tid;
            int row = idx >> 2;
            int c4  = idx & 3;
            float4 v = make_float4(0.f, 0.f, 0.f, 0.f);
            if (brow + row < M)
                v = *(const float4*)(A + (size_t)(brow + row) * K + k0 + c4 * 4);
            As[c4 * 4 + 0][row] = v.x;
            As[c4 * 4 + 1][row] = v.y;
            As[c4 * 4 + 2][row] = v.z;
            As[c4 * 4 + 3][row] = v.w;
        }
#pragma unroll
        for (int i = 0; i < 2; i++) {
            int idx = i * 256 + tid;
            int row = idx >> 5;
            int c4  = idx & 31;
            float4 v = *(const float4*)(B + (size_t)(k0 + row) * N + bcol + c4 * 4);
            *(float4*)&Bs[row][c4 * 4] = v;
        }
        __syncthreads();

#pragma unroll
        for (int kk = 0; kk < 16; kk++) {
            float a[8], b[8];
#pragma unroll
            for (int i = 0; i < 8; i++) a[i] = As[kk][trow + i];
            *(float4*)&b[0] = *(const float4*)&Bs[kk][tcol];
            *(float4*)&b[4] = *(const float4*)&Bs[kk][tcol + 4];
#pragma unroll
            for (int i = 0; i < 8; i++)
#pragma unroll
                for (int j = 0; j < 8; j++)
                    acc[i][j] = fmaf(a[i], b[j], acc[i][j]);
        }
        __syncthreads();
    }

#pragma unroll
    for (int i = 0; i < 8; i++) {
        int row = brow + trow + i;
        if (row < M) {
#pragma unroll
            for (int j = 0; j < 8; j += 4) {
                float4 v = make_float4(acc[i][j], acc[i][j + 1],
                                       acc[i][j + 2], acc[i][j + 3]);
                *(float4*)(C + (size_t)row * N + bcol + tcol + j) = v;
            }
        }
    }
}

// ---------------------------------------------------------------------------
// out[i,:] = h[i,:] * dinv[i]^2   (self-loop term; also initializes buffer)
// ---------------------------------------------------------------------------
__global__ void k_self_init(const float* __restrict__ h,
                            const float* __restrict__ dinv,
                            float* __restrict__ out, int C) {
    int idx  = blockIdx.x * blockDim.x + threadIdx.x;
    int node = idx / C;
    float di = dinv[node];
    out[idx] = h[idx] * (di * di);
}

// ---------------------------------------------------------------------------
// scatter-add over edges: out[dst,:] += h[src,:] * dinv[src]*dinv[dst]
// float4 load + 4 scalar atomicAdds (fire-and-forget REDG in SASS)
// ---------------------------------------------------------------------------
__global__ void k_scatter(const float* __restrict__ h,
                          const void* __restrict__ ei,
                          const float* __restrict__ dinv,
                          float* __restrict__ out, int C) {
    int tpe  = C >> 2;                       // threads per edge (float4 lanes)
    int epb  = blockDim.x / tpe;             // edges per block
    int e    = blockIdx.x * epb + threadIdx.x / tpe;
    if (e >= NE) return;
    int lane = threadIdx.x & (tpe - 1);

    int is64 = g_is64;
    int s = edge_idx(ei, (size_t)e, is64);
    int d = edge_idx(ei, (size_t)NE + e, is64);
    float w = dinv[s] * dinv[d];

    float4 v = *(const float4*)(h + (size_t)s * C + lane * 4);
    float* o = out + (size_t)d * C + lane * 4;
    atomicAdd(o + 0, v.x * w);
    atomicAdd(o + 1, v.y * w);
    atomicAdd(o + 2, v.z * w);
    atomicAdd(o + 3, v.w * w);
}

// ---------------------------------------------------------------------------
// bias (+relu) epilogues
// ---------------------------------------------------------------------------
__global__ void k_bias_relu(float* __restrict__ a, const float* __restrict__ b, int Cmask) {
    int idx = blockIdx.x * blockDim.x + threadIdx.x;
    float v = a[idx] + b[idx & Cmask];
    a[idx] = fmaxf(v, 0.0f);
}

__global__ void k_bias(float* __restrict__ a, const float* __restrict__ b, int Cmask) {
    int idx = blockIdx.x * blockDim.x + threadIdx.x;
    a[idx] = a[idx] + b[idx & Cmask];
}

// ---------------------------------------------------------------------------
extern "C" void kernel_launch(void* const* d_in, const int* in_sizes, int n_in,
                              void* d_out, int out_size) {
    const float* x  = (const float*)d_in[0];
    const void*  ei = d_in[1];
    const float* W1 = (const float*)d_in[2];
    const float* b1 = (const float*)d_in[3];
    const float* W2 = (const float*)d_in[4];
    const float* b2 = (const float*)d_in[5];
    float*       out = (float*)d_out;

    float *deg, *h1, *agg1, *h2;
    cudaGetSymbolAddress((void**)&deg,  g_deg);
    cudaGetSymbolAddress((void**)&h1,   g_h1);
    cudaGetSymbolAddress((void**)&agg1, g_agg1);
    cudaGetSymbolAddress((void**)&h2,   g_h2);

    // dtype detection
    k_flag_init<<<1, 1>>>();
    k_detect   <<<1, 256>>>((const unsigned int*)ei);

    // normalization
    k_deg_init <<<(NN + 255) / 256, 256>>>(deg);
    k_deg_accum<<<(NE + 255) / 256, 256>>>(ei, deg);
    k_dinv     <<<(NN + 255) / 256, 256>>>(deg);

    // ---- layer 1 ----
    dim3 g1((NN + 127) / 128, HID / 128);
    sgemm_128x128<<<g1, 256>>>(x, W1, h1, NN, HID, IN_CH);
    k_self_init<<<(size_t)NN * HID / 256, 256>>>(h1, deg, agg1, HID);
    k_scatter  <<<NE / (256 / (HID / 4)), 256>>>(h1, ei, deg, agg1, HID);
    k_bias_relu<<<(size_t)NN * HID / 256, 256>>>(agg1, b1, HID - 1);

    // ---- layer 2 ----
    dim3 g2((NN + 127) / 128, OUTC / 128);
    sgemm_128x128<<<g2, 256>>>(agg1, W2, h2, NN, OUTC, HID);
    k_self_init<<<(size_t)NN * OUTC / 256, 256>>>(h2, deg, out, OUTC);
    k_scatter  <<<NE / (256 / (OUTC / 4)), 256>>>(h2, ei, deg, out, OUTC);
    k_bias     <<<(size_t)NN * OUTC / 256, 256>>>(out, b2, OUTC - 1);
}

// round 4
// speedup vs baseline: 1.0064x; 1.0064x over previous
#include <cuda_runtime.h>

#define NN 50000
#define NE 800000
#define IN_CH 512
#define HID 256
#define OUTC 128

// ---- scratch (static device globals; no allocations allowed) ----
__device__ float g_deg[NN];                       // deg -> dinv in place
__device__ float g_h1[(size_t)NN * HID];         // x @ W1
__device__ float g_agg1[(size_t)NN * HID];       // aggregated + relu
__device__ float g_h2[(size_t)NN * OUTC];        // agg1 @ W2
__device__ int   g_is64;                          // edge_index dtype flag

// ---------------------------------------------------------------------------
// dtype detection: int64 node ids (< 2^31) have all-zero odd 32-bit words;
// random int32 ids in [0, 50000) cannot. Deterministic pure function of input.
// ---------------------------------------------------------------------------
__global__ void k_flag_init() { g_is64 = 1; }

__global__ void k_detect(const unsigned int* __restrict__ w) {
    unsigned acc = 0;
    for (int i = threadIdx.x; i < 2048; i += blockDim.x) acc |= w[2 * i + 1];
    if (acc) g_is64 = 0;                      // any nonzero odd word -> int32
}

__device__ __forceinline__ int edge_idx(const void* ei, size_t pos, int is64) {
    long long v = is64 ? ((const long long*)ei)[pos]
                       : (long long)((const int*)ei)[pos];
    int i = (int)v;
    i = i < 0 ? 0 : (i >= NN ? NN - 1 : i);   // clamp: trap insurance
    return i;
}

// ---------------------------------------------------------------------------
// degree / normalization
// ---------------------------------------------------------------------------
__global__ void k_deg_init(float* deg) {
    int i = blockIdx.x * blockDim.x + threadIdx.x;
    if (i < NN) deg[i] = 1.0f;   // self-loop contributes 1
}

__global__ void k_deg_accum(const void* __restrict__ ei, float* deg) {
    int e = blockIdx.x * blockDim.x + threadIdx.x;
    if (e >= NE) return;
    int is64 = g_is64;
    atomicAdd(&deg[edge_idx(ei, (size_t)NE + e, is64)], 1.0f);   // dst row
}

__global__ void k_dinv(float* deg) {
    int i = blockIdx.x * blockDim.x + threadIdx.x;
    if (i < NN) deg[i] = rsqrtf(deg[i]);   // deg >= 1 always (self-loops)
}

// ---------------------------------------------------------------------------
// SGEMM: C[M,N] = A[M,K] @ B[K,N], fp32, 128x128x16 tile, 8x8 per thread
// ---------------------------------------------------------------------------
__global__ __launch_bounds__(256, 2)
void sgemm_128x128(const float* __restrict__ A, const float* __restrict__ B,
                   float* __restrict__ C, int M, int N, int K) {
    __shared__ float As[16][129];                 // transposed, padded
    __shared__ __align__(16) float Bs[16][128];

    const int tid  = threadIdx.x;
    const int brow = blockIdx.x * 128;
    const int bcol = blockIdx.y * 128;
    const int trow = (tid >> 4) * 8;
    const int tcol = (tid & 15) * 8;

    float acc[8][8];
#pragma unroll
    for (int i = 0; i < 8; i++)
#pragma unroll
        for (int j = 0; j < 8; j++) acc[i][j] = 0.0f;

    for (int k0 = 0; k0 < K; k0 += 16) {
#pragma unroll
        for (int i = 0; i < 2; i++) {
            int idx = i * 256 + tid;
            int row = idx >> 2;
            int c4  = idx & 3;
            float4 v = make_float4(0.f, 0.f, 0.f, 0.f);
            if (brow + row < M)
                v = *(const float4*)(A + (size_t)(brow + row) * K + k0 + c4 * 4);
            As[c4 * 4 + 0][row] = v.x;
            As[c4 * 4 + 1][row] = v.y;
            As[c4 * 4 + 2][row] = v.z;
            As[c4 * 4 + 3][row] = v.w;
        }
#pragma unroll
        for (int i = 0; i < 2; i++) {
            int idx = i * 256 + tid;
            int row = idx >> 5;
            int c4  = idx & 31;
            float4 v = *(const float4*)(B + (size_t)(k0 + row) * N + bcol + c4 * 4);
            *(float4*)&Bs[row][c4 * 4] = v;
        }
        __syncthreads();

#pragma unroll
        for (int kk = 0; kk < 16; kk++) {
            float a[8], b[8];
#pragma unroll
            for (int i = 0; i < 8; i++) a[i] = As[kk][trow + i];
            *(float4*)&b[0] = *(const float4*)&Bs[kk][tcol];
            *(float4*)&b[4] = *(const float4*)&Bs[kk][tcol + 4];
#pragma unroll
            for (int i = 0; i < 8; i++)
#pragma unroll
                for (int j = 0; j < 8; j++)
                    acc[i][j] = fmaf(a[i], b[j], acc[i][j]);
        }
        __syncthreads();
    }

#pragma unroll
    for (int i = 0; i < 8; i++) {
        int row = brow + trow + i;
        if (row < M) {
#pragma unroll
            for (int j = 0; j < 8; j += 4) {
                float4 v = make_float4(acc[i][j], acc[i][j + 1],
                                       acc[i][j + 2], acc[i][j + 3]);
                *(float4*)(C + (size_t)row * N + bcol + tcol + j) = v;
            }
        }
    }
}

// ---------------------------------------------------------------------------
// out[i,:] = h[i,:] * dinv[i]^2   (self-loop term; also initializes buffer)
// ---------------------------------------------------------------------------
__global__ void k_self_init(const float* __restrict__ h,
                            const float* __restrict__ dinv,
                            float* __restrict__ out, int C) {
    int idx  = blockIdx.x * blockDim.x + threadIdx.x;
    int node = idx / C;
    float di = dinv[node];
    out[idx] = h[idx] * (di * di);
}

// ---------------------------------------------------------------------------
// scatter-add over edges: out[dst,:] += h[src,:] * dinv[src]*dinv[dst]
// float4 load + 4 scalar atomicAdds (fire-and-forget REDG in SASS)
// ---------------------------------------------------------------------------
__global__ void k_scatter(const float* __restrict__ h,
                          const void* __restrict__ ei,
                          const float* __restrict__ dinv,
                          float* __restrict__ out, int C) {
    int tpe  = C >> 2;                       // threads per edge (float4 lanes)
    int epb  = blockDim.x / tpe;             // edges per block
    int e    = blockIdx.x * epb + threadIdx.x / tpe;
    if (e >= NE) return;
    int lane = threadIdx.x & (tpe - 1);

    int is64 = g_is64;
    int s = edge_idx(ei, (size_t)e, is64);
    int d = edge_idx(ei, (size_t)NE + e, is64);
    float w = dinv[s] * dinv[d];

    float4 v = *(const float4*)(h + (size_t)s * C + lane * 4);
    float* o = out + (size_t)d * C + lane * 4;
    atomicAdd(o + 0, v.x * w);
    atomicAdd(o + 1, v.y * w);
    atomicAdd(o + 2, v.z * w);
    atomicAdd(o + 3, v.w * w);
}

// ---------------------------------------------------------------------------
// bias (+relu) epilogues
// ---------------------------------------------------------------------------
__global__ void k_bias_relu(float* __restrict__ a, const float* __restrict__ b, int Cmask) {
    int idx = blockIdx.x * blockDim.x + threadIdx.x;
    float v = a[idx] + b[idx & Cmask];
    a[idx] = fmaxf(v, 0.0f);
}

__global__ void k_bias(float* __restrict__ a, const float* __restrict__ b, int Cmask) {
    int idx = blockIdx.x * blockDim.x + threadIdx.x;
    a[idx] = a[idx] + b[idx & Cmask];
}

// ---------------------------------------------------------------------------
extern "C" void kernel_launch(void* const* d_in, const int* in_sizes, int n_in,
                              void* d_out, int out_size) {
    const float* x  = (const float*)d_in[0];
    const void*  ei = d_in[1];
    const float* W1 = (const float*)d_in[2];
    const float* b1 = (const float*)d_in[3];
    const float* W2 = (const float*)d_in[4];
    const float* b2 = (const float*)d_in[5];
    float*       out = (float*)d_out;

    float *deg, *h1, *agg1, *h2;
    cudaGetSymbolAddress((void**)&deg,  g_deg);
    cudaGetSymbolAddress((void**)&h1,   g_h1);
    cudaGetSymbolAddress((void**)&agg1, g_agg1);
    cudaGetSymbolAddress((void**)&h2,   g_h2);

    // dtype detection
    k_flag_init<<<1, 1>>>();
    k_detect   <<<1, 256>>>((const unsigned int*)ei);

    // normalization
    k_deg_init <<<(NN + 255) / 256, 256>>>(deg);
    k_deg_accum<<<(NE + 255) / 256, 256>>>(ei, deg);
    k_dinv     <<<(NN + 255) / 256, 256>>>(deg);

    // ---- layer 1 ----
    dim3 g1((NN + 127) / 128, HID / 128);
    sgemm_128x128<<<g1, 256>>>(x, W1, h1, NN, HID, IN_CH);
    k_self_init<<<(size_t)NN * HID / 256, 256>>>(h1, deg, agg1, HID);
    k_scatter  <<<NE / (256 / (HID / 4)), 256>>>(h1, ei, deg, agg1, HID);
    k_bias_relu<<<(size_t)NN * HID / 256, 256>>>(agg1, b1, HID - 1);

    // ---- layer 2 ----
    dim3 g2((NN + 127) / 128, OUTC / 128);
    sgemm_128x128<<<g2, 256>>>(agg1, W2, h2, NN, OUTC, HID);
    k_self_init<<<(size_t)NN * OUTC / 256, 256>>>(h2, deg, out, OUTC);
    k_scatter  <<<NE / (256 / (OUTC / 4)), 256>>>(h2, ei, deg, out, OUTC);
    k_bias     <<<(size_t)NN * OUTC / 256, 256>>>(out, b2, OUTC - 1);
}

// round 5
// speedup vs baseline: 1.9932x; 1.9806x over previous
#include <cuda_runtime.h>

#define NN 50000
#define NE 800000
#define IN_CH 512
#define HID 256
#define OUTC 128

// ---- scratch (static device globals; no allocations allowed) ----
__device__ float g_dinv[NN];
__device__ int   g_cnt[NN];                      // in-degree (excl. self)
__device__ int   g_rowptr[NN + 1];
__device__ int   g_cursor[NN];
__device__ int   g_esrc[NE];                     // src ids sorted by dst
__device__ float g_h1[(size_t)NN * HID];         // x @ W1
__device__ float g_agg1[(size_t)NN * HID];       // aggregated + relu
__device__ float g_h2[(size_t)NN * OUTC];        // agg1 @ W2
__device__ int   g_is64;                         // edge_index dtype flag

// ---------------------------------------------------------------------------
// dtype detection: int64 ids (< 2^31) have all-zero odd 32-bit words.
// ---------------------------------------------------------------------------
__global__ void k_flag_init() { g_is64 = 1; }

__global__ void k_detect(const unsigned int* __restrict__ w) {
    unsigned acc = 0;
    for (int i = threadIdx.x; i < 2048; i += blockDim.x) acc |= w[2 * i + 1];
    if (acc) g_is64 = 0;
}

__device__ __forceinline__ int edge_idx(const void* ei, size_t pos, int is64) {
    int i = is64 ? (int)((const long long*)ei)[pos] : ((const int*)ei)[pos];
    i = i < 0 ? 0 : (i >= NN ? NN - 1 : i);      // clamp: trap insurance
    return i;
}

// ---------------------------------------------------------------------------
// CSR build
// ---------------------------------------------------------------------------
__global__ void k_zero_cnt() {
    int i = blockIdx.x * blockDim.x + threadIdx.x;
    if (i < NN) g_cnt[i] = 0;
}

__global__ void k_count(const void* __restrict__ ei) {
    int e = blockIdx.x * blockDim.x + threadIdx.x;
    if (e >= NE) return;
    atomicAdd(&g_cnt[edge_idx(ei, (size_t)NE + e, g_is64)], 1);
}

__global__ void k_dinv_from_cnt() {
    int i = blockIdx.x * blockDim.x + threadIdx.x;
    if (i < NN) g_dinv[i] = rsqrtf((float)g_cnt[i] + 1.0f);  // +1 self-loop
}

// single-block exclusive scan of g_cnt -> g_rowptr / g_cursor
__global__ void k_scan() {
    __shared__ int s[1024];
    const int t  = threadIdx.x;
    const int CH = (NN + 1023) / 1024;           // 49
    const int base = t * CH;
    int sum = 0;
    for (int i = 0; i < CH; i++) {
        int idx = base + i;
        sum += (idx < NN) ? g_cnt[idx] : 0;
    }
    s[t] = sum;
    __syncthreads();
    for (int off = 1; off < 1024; off <<= 1) {   // Hillis-Steele inclusive
        int v = (t >= off) ? s[t - off] : 0;
        __syncthreads();
        s[t] += v;
        __syncthreads();
    }
    int run = (t == 0) ? 0 : s[t - 1];
    for (int i = 0; i < CH; i++) {
        int idx = base + i;
        if (idx < NN) {
            g_rowptr[idx] = run;
            g_cursor[idx] = run;
            run += g_cnt[idx];
        }
    }
    if (t == 1023) g_rowptr[NN] = s[1023];
}

__global__ void k_fill(const void* __restrict__ ei) {
    int e = blockIdx.x * blockDim.x + threadIdx.x;
    if (e >= NE) return;
    int is64 = g_is64;
    int s = edge_idx(ei, (size_t)e, is64);
    int d = edge_idx(ei, (size_t)NE + e, is64);
    int pos = atomicAdd(&g_cursor[d], 1);
    g_esrc[pos] = s;
}

// ---------------------------------------------------------------------------
// SGEMM: C[M,N] = A[M,K] @ B[K,N], fp32, 128x128x16 tile, 8x8 per thread
// ---------------------------------------------------------------------------
__global__ __launch_bounds__(256, 2)
void sgemm_128x128(const float* __restrict__ A, const float* __restrict__ B,
                   float* __restrict__ C, int M, int N, int K) {
    __shared__ float As[16][129];
    __shared__ __align__(16) float Bs[16][128];

    const int tid  = threadIdx.x;
    const int brow = blockIdx.x * 128;
    const int bcol = blockIdx.y * 128;
    const int trow = (tid >> 4) * 8;
    const int tcol = (tid & 15) * 8;

    float acc[8][8];
#pragma unroll
    for (int i = 0; i < 8; i++)
#pragma unroll
        for (int j = 0; j < 8; j++) acc[i][j] = 0.0f;

    for (int k0 = 0; k0 < K; k0 += 16) {
#pragma unroll
        for (int i = 0; i < 2; i++) {
            int idx = i * 256 + tid;
            int row = idx >> 2;
            int c4  = idx & 3;
            float4 v = make_float4(0.f, 0.f, 0.f, 0.f);
            if (brow + row < M)
                v = *(const float4*)(A + (size_t)(brow + row) * K + k0 + c4 * 4);
            As[c4 * 4 + 0][row] = v.x;
            As[c4 * 4 + 1][row] = v.y;
            As[c4 * 4 + 2][row] = v.z;
            As[c4 * 4 + 3][row] = v.w;
        }
#pragma unroll
        for (int i = 0; i < 2; i++) {
            int idx = i * 256 + tid;
            int row = idx >> 5;
            int c4  = idx & 31;
            float4 v = *(const float4*)(B + (size_t)(k0 + row) * N + bcol + c4 * 4);
            *(float4*)&Bs[row][c4 * 4] = v;
        }
        __syncthreads();

#pragma unroll
        for (int kk = 0; kk < 16; kk++) {
            float a[8], b[8];
#pragma unroll
            for (int i = 0; i < 8; i++) a[i] = As[kk][trow + i];
            *(float4*)&b[0] = *(const float4*)&Bs[kk][tcol];
            *(float4*)&b[4] = *(const float4*)&Bs[kk][tcol + 4];
#pragma unroll
            for (int i = 0; i < 8; i++)
#pragma unroll
                for (int j = 0; j < 8; j++)
                    acc[i][j] = fmaf(a[i], b[j], acc[i][j]);
        }
        __syncthreads();
    }

#pragma unroll
    for (int i = 0; i < 8; i++) {
        int row = brow + trow + i;
        if (row < M) {
#pragma unroll
            for (int j = 0; j < 8; j += 4) {
                float4 v = make_float4(acc[i][j], acc[i][j + 1],
                                       acc[i][j + 2], acc[i][j + 3]);
                *(float4*)(C + (size_t)row * N + bcol + tcol + j) = v;
            }
        }
    }
}

// ---------------------------------------------------------------------------
// fused CSR gather: out[d,:] = relu?( dinv[d]^2 * h[d,:]
//                              + sum_e dinv[src]*dinv[d] * h[src,:] + bias )
// C = feature width, L = C/4 lanes per node, 256/L nodes per block
// ---------------------------------------------------------------------------
template <int C, bool RELU>
__global__ __launch_bounds__(256)
void k_gather(const float* __restrict__ h,
              const float* __restrict__ bias,
              float* __restrict__ out) {
    constexpr int L   = C / 4;
    constexpr int NPB = 256 / L;
    int node = blockIdx.x * NPB + threadIdx.x / L;
    if (node >= NN) return;
    int lane = threadIdx.x % L;

    const float4* h4 = (const float4*)h;
    float dd = g_dinv[node];

    float4 self = h4[(size_t)node * L + lane];
    float wself = dd * dd;
    float4 acc;
    acc.x = self.x * wself; acc.y = self.y * wself;
    acc.z = self.z * wself; acc.w = self.w * wself;

    int beg = g_rowptr[node];
    int end = g_rowptr[node + 1];
    for (int e = beg; e < end; e++) {
        int s   = __ldg(&g_esrc[e]);
        float w = __ldg(&g_dinv[s]) * dd;
        float4 v = h4[(size_t)s * L + lane];
        acc.x = fmaf(v.x, w, acc.x);
        acc.y = fmaf(v.y, w, acc.y);
        acc.z = fmaf(v.z, w, acc.z);
        acc.w = fmaf(v.w, w, acc.w);
    }

    float4 b = ((const float4*)bias)[lane];
    acc.x += b.x; acc.y += b.y; acc.z += b.z; acc.w += b.w;
    if (RELU) {
        acc.x = fmaxf(acc.x, 0.f); acc.y = fmaxf(acc.y, 0.f);
        acc.z = fmaxf(acc.z, 0.f); acc.w = fmaxf(acc.w, 0.f);
    }
    ((float4*)out)[(size_t)node * L + lane] = acc;
}

// ---------------------------------------------------------------------------
extern "C" void kernel_launch(void* const* d_in, const int* in_sizes, int n_in,
                              void* d_out, int out_size) {
    const float* x  = (const float*)d_in[0];
    const void*  ei = d_in[1];
    const float* W1 = (const float*)d_in[2];
    const float* b1 = (const float*)d_in[3];
    const float* W2 = (const float*)d_in[4];
    const float* b2 = (const float*)d_in[5];
    float*       out = (float*)d_out;

    float *h1, *agg1, *h2;
    cudaGetSymbolAddress((void**)&h1,   g_h1);
    cudaGetSymbolAddress((void**)&agg1, g_agg1);
    cudaGetSymbolAddress((void**)&h2,   g_h2);

    // dtype detection + CSR build
    k_flag_init<<<1, 1>>>();
    k_detect   <<<1, 256>>>((const unsigned int*)ei);
    k_zero_cnt <<<(NN + 255) / 256, 256>>>();
    k_count    <<<(NE + 255) / 256, 256>>>(ei);
    k_dinv_from_cnt<<<(NN + 255) / 256, 256>>>();
    k_scan     <<<1, 1024>>>();
    k_fill     <<<(NE + 255) / 256, 256>>>(ei);

    // ---- layer 1: GEMM + fused gather/bias/relu ----
    dim3 g1((NN + 127) / 128, HID / 128);
    sgemm_128x128<<<g1, 256>>>(x, W1, h1, NN, HID, IN_CH);
    k_gather<HID, true><<<(NN + 3) / 4, 256>>>(h1, b1, agg1);

    // ---- layer 2: GEMM + fused gather/bias ----
    dim3 g2((NN + 127) / 128, OUTC / 128);
    sgemm_128x128<<<g2, 256>>>(agg1, W2, h2, NN, OUTC, HID);
    k_gather<OUTC, false><<<(NN + 7) / 8, 256>>>(h2, b2, out);
}